// round 4
// baseline (speedup 1.0000x reference)
#include <cuda_runtime.h>
#include <math.h>
#include <stdint.h>

// Batched log(M) for SPD 64x64 matrices, spectrum in [1, 6]:
// degree-8 Chebyshev approx of log on [1,6] in T = (M - 3.5 I)/2.5,
// Paterson-Stockmeyer s=3 (4 matmuls: T2, T3, 2 Horner steps),
// inner product via packed fma.rn.f32x2, 4x8 register tiles, 128 thr/matrix.

constexpr int DEG = 8;
constexpr int S   = 64;        // smem row stride (floats)
constexpr int MSZ = 64 * S;    // floats per 64x64 buffer

struct Poly { float a[DEG + 1]; };

typedef unsigned long long u64;

__device__ __forceinline__ u64 splat2(float x) {
    u64 r; asm("mov.b64 %0, {%1, %1};" : "=l"(r) : "f"(x)); return r;
}
__device__ __forceinline__ u64 pack2(float lo, float hi) {
    u64 r; asm("mov.b64 %0, {%1, %2};" : "=l"(r) : "f"(lo), "f"(hi)); return r;
}
__device__ __forceinline__ void fma2(u64& d, u64 a, u64 b) {
    asm("fma.rn.f32x2 %0, %1, %2, %0;" : "+l"(d) : "l"(a), "l"(b));
}
__device__ __forceinline__ void add2(u64& d, u64 a) {
    asm("add.rn.f32x2 %0, %0, %1;" : "+l"(d) : "l"(a));
}

// Thread tile: 4 rows x 8 cols (4 packed pairs per row).
// acc[r][p] = (C[i0+r][j0+2p], C[i0+r][j0+2p+1]),  C = A^T B (= A B, A sym).
// Per warp-k: A is 1 LDS.128 broadcast (1 wavefront), B is 2 LDS.128 (2 wf)
// feeding 16 FFMA2 -> FMA-bound, LDS well under crossbar.
__device__ __forceinline__ void mm64(const float* __restrict__ A,
                                     const float* __restrict__ B,
                                     int i0, int j0, u64 acc[4][4]) {
#pragma unroll
    for (int r = 0; r < 4; ++r)
#pragma unroll
        for (int p = 0; p < 4; ++p) acc[r][p] = 0ull;

    const float* ap = A + i0;
    const float* bp = B + j0;
#pragma unroll 16
    for (int k = 0; k < 64; ++k) {
        const float4     av = *reinterpret_cast<const float4*>(ap + k * S);
        const ulonglong2 b0 = *reinterpret_cast<const ulonglong2*>(bp + k * S);
        const ulonglong2 b1 = *reinterpret_cast<const ulonglong2*>(bp + k * S + 4);
        const u64 a0 = splat2(av.x), a1 = splat2(av.y);
        const u64 a2 = splat2(av.z), a3 = splat2(av.w);
        fma2(acc[0][0], a0, b0.x); fma2(acc[0][1], a0, b0.y);
        fma2(acc[0][2], a0, b1.x); fma2(acc[0][3], a0, b1.y);
        fma2(acc[1][0], a1, b0.x); fma2(acc[1][1], a1, b0.y);
        fma2(acc[1][2], a1, b1.x); fma2(acc[1][3], a1, b1.y);
        fma2(acc[2][0], a2, b0.x); fma2(acc[2][1], a2, b0.y);
        fma2(acc[2][2], a2, b1.x); fma2(acc[2][3], a2, b1.y);
        fma2(acc[3][0], a3, b0.x); fma2(acc[3][1], a3, b0.y);
        fma2(acc[3][2], a3, b1.x); fma2(acc[3][3], a3, b1.y);
    }
}

// acc += c0*I + c1*T + c2*T2 on this thread's 4x8 tile.
__device__ __forceinline__ void addpoly(u64 acc[4][4],
                                        const float* __restrict__ T,
                                        const float* __restrict__ T2,
                                        float c0, float c1, float c2,
                                        int i0, int j0) {
    const u64 c1s = splat2(c1), c2s = splat2(c2);
#pragma unroll
    for (int r = 0; r < 4; ++r) {
        const float* tr = T  + (i0 + r) * S + j0;
        const float* sr = T2 + (i0 + r) * S + j0;
        const ulonglong2 t0 = *reinterpret_cast<const ulonglong2*>(tr);
        const ulonglong2 t1 = *reinterpret_cast<const ulonglong2*>(tr + 4);
        const ulonglong2 s0 = *reinterpret_cast<const ulonglong2*>(sr);
        const ulonglong2 s1 = *reinterpret_cast<const ulonglong2*>(sr + 4);
        fma2(acc[r][0], c1s, t0.x); fma2(acc[r][1], c1s, t0.y);
        fma2(acc[r][2], c1s, t1.x); fma2(acc[r][3], c1s, t1.y);
        fma2(acc[r][0], c2s, s0.x); fma2(acc[r][1], c2s, s0.y);
        fma2(acc[r][2], c2s, s1.x); fma2(acc[r][3], c2s, s1.y);
    }
    // diagonal element (i,i) lands in this tile iff 0 <= (i0+r)-j0 < 8
#pragma unroll
    for (int r = 0; r < 4; ++r) {
        const int cc = i0 + r - j0;
        if (cc >= 0 && cc < 8) {
            const u64 d = (cc & 1) ? pack2(0.0f, c0) : pack2(c0, 0.0f);
            add2(acc[r][cc >> 1], d);
        }
    }
}

__device__ __forceinline__ void store_tile(float* __restrict__ C, int stride,
                                           int i0, int j0, const u64 acc[4][4]) {
#pragma unroll
    for (int r = 0; r < 4; ++r) {
        float* cr = C + (i0 + r) * stride + j0;
        *reinterpret_cast<ulonglong2*>(cr)     = make_ulonglong2(acc[r][0], acc[r][1]);
        *reinterpret_cast<ulonglong2*>(cr + 4) = make_ulonglong2(acc[r][2], acc[r][3]);
    }
}

__global__ __launch_bounds__(128, 3)
void logm_poly_kernel(const float* __restrict__ gin,
                      float* __restrict__ gout,
                      Poly P) {
    extern __shared__ float sm[];
    float* T  = sm;
    float* T2 = sm + 1 * MSZ;
    float* T3 = sm + 2 * MSZ;
    float* AC = sm + 3 * MSZ;

    const int tid = threadIdx.x;
    const int i0  = (tid >> 3) * 4;     // 16 row groups of 4
    const int j0  = (tid & 7) * 8;      //  8 col groups of 8
    const float* gm = gin  + (size_t)blockIdx.x * 4096;
    float*       go = gout + (size_t)blockIdx.x * 4096;

    const float inv_beta = 1.0f / 2.5f;
    const float alpha    = 3.5f;

    // T = (M - alpha*I) / beta     (lambda(T) in [-1, 1])
    for (int e = tid; e < 1024; e += 128) {
        float4 v = reinterpret_cast<const float4*>(gm)[e];
        const int row = e >> 4;
        const int c0  = (e & 15) * 4;
        if (row >= c0 && row < c0 + 4) {
            float* vv = &v.x;
            vv[row - c0] -= alpha;
        }
        v.x *= inv_beta; v.y *= inv_beta; v.z *= inv_beta; v.w *= inv_beta;
        *reinterpret_cast<float4*>(T + row * S + c0) = v;
    }
    __syncthreads();

    u64 acc[4][4];

    // T2 = T*T
    mm64(T, T, i0, j0, acc);
    store_tile(T2, S, i0, j0, acc);
    __syncthreads();

    // T3 = T2*T ; AC = a6*I + a7*T + a8*T2  (reads only T, T2)
    mm64(T2, T, i0, j0, acc);
    store_tile(T3, S, i0, j0, acc);
    {
        u64 c2[4][4];
#pragma unroll
        for (int r = 0; r < 4; ++r)
#pragma unroll
            for (int p = 0; p < 4; ++p) c2[r][p] = 0ull;
        addpoly(c2, T, T2, P.a[6], P.a[7], P.a[8], i0, j0);
        store_tile(AC, S, i0, j0, c2);
    }
    __syncthreads();

    // Horner step 1: AC = AC*T3 + a3*I + a4*T + a5*T2
    mm64(AC, T3, i0, j0, acc);
    addpoly(acc, T, T2, P.a[3], P.a[4], P.a[5], i0, j0);
    __syncthreads();                       // all reads of old AC complete
    store_tile(AC, S, i0, j0, acc);
    __syncthreads();

    // Horner step 2 (final): out = AC*T3 + a0*I + a1*T + a2*T2 -> global
    mm64(AC, T3, i0, j0, acc);
    addpoly(acc, T, T2, P.a[0], P.a[1], P.a[2], i0, j0);
    store_tile(go, 64, i0, j0, acc);
}

extern "C" void kernel_launch(void* const* d_in, const int* in_sizes, int n_in,
                              void* d_out, int out_size) {
    const float* in = (const float*)d_in[0];
    float* out = (float*)d_out;
    const int nmat = in_sizes[0] / 4096;   // 8192 matrices of 64x64

    // Chebyshev coefficients of log on [1,6], converted to monomial basis.
    Poly P;
    {
        const double alpha = 3.5, beta = 2.5;
        const double r = (alpha - sqrt(alpha * alpha - beta * beta)) / beta;
        double c[DEG + 1];
        c[0] = log(alpha / (1.0 + r * r));
        double rk = 1.0;
        for (int k = 1; k <= DEG; ++k) {
            rk *= r;
            c[k] = ((k & 1) ? 2.0 : -2.0) * rk / (double)k;
        }
        double mono[DEG + 1], Tm1[DEG + 1], Tc[DEG + 1], Tn[DEG + 1];
        for (int j = 0; j <= DEG; ++j) { mono[j] = 0; Tm1[j] = 0; Tc[j] = 0; }
        Tm1[0] = 1.0;            // T0
        Tc[1]  = 1.0;            // T1
        for (int j = 0; j <= DEG; ++j) mono[j] = c[0] * Tm1[j] + c[1] * Tc[j];
        for (int k = 2; k <= DEG; ++k) {
            for (int j = 0; j <= DEG; ++j) {
                double t = -Tm1[j];
                if (j > 0) t += 2.0 * Tc[j - 1];
                Tn[j] = t;
            }
            for (int j = 0; j <= DEG; ++j) {
                mono[j] += c[k] * Tn[j];
                Tm1[j] = Tc[j];
                Tc[j]  = Tn[j];
            }
        }
        for (int j = 0; j <= DEG; ++j) P.a[j] = (float)mono[j];
    }

    const size_t smem_bytes = 4 * MSZ * sizeof(float);   // 64 KB
    cudaFuncSetAttribute(logm_poly_kernel,
                         cudaFuncAttributeMaxDynamicSharedMemorySize,
                         (int)smem_bytes);
    logm_poly_kernel<<<nmat, 128, smem_bytes>>>(in, out, P);
}

// round 5
// speedup vs baseline: 1.7000x; 1.7000x over previous
#include <cuda_runtime.h>
#include <math.h>
#include <stdint.h>

// Batched log(M) for SPD 64x64 matrices, spectrum in [1, 6]:
// degree-8 Chebyshev approx of log on [1,6] in T = (M - 3.5 I)/2.5,
// Paterson-Stockmeyer s=2 (4 matmuls: T2 + 3 Horner steps),
// packed fma.rn.f32x2, 256 threads, 4x4 tiles, balanced 4x8 lane map.

constexpr int DEG = 8;
constexpr int S   = 64;        // smem row stride (floats)
constexpr int MSZ = 64 * S;    // floats per 64x64 buffer

struct Poly { float a[DEG + 1]; };

typedef unsigned long long u64;

__device__ __forceinline__ u64 splat2(float x) {
    u64 r; asm("mov.b64 %0, {%1, %1};" : "=l"(r) : "f"(x)); return r;
}
__device__ __forceinline__ u64 pack2(float lo, float hi) {
    u64 r; asm("mov.b64 %0, {%1, %2};" : "=l"(r) : "f"(lo), "f"(hi)); return r;
}
__device__ __forceinline__ void fma2(u64& d, u64 a, u64 b) {
    asm("fma.rn.f32x2 %0, %1, %2, %0;" : "+l"(d) : "l"(a), "l"(b));
}
__device__ __forceinline__ void add2(u64& d, u64 a) {
    asm("add.rn.f32x2 %0, %0, %1;" : "+l"(d) : "l"(a));
}

// Thread tile 4x4: acc[r][p] = (C[i0+r][j0+2p], C[i0+r][j0+2p+1]).
// C = A^T B (= A B for symmetric A); both operands read as LDS.128 row reads.
// Lane map (set in kernel): warp covers 16 rows x 32 cols -> per warp-k
// distinct smem bytes: A 64B + B 128B = 192B.
__device__ __forceinline__ void mm64(const float* __restrict__ A,
                                     const float* __restrict__ B,
                                     int i0, int j0, u64 acc[4][2]) {
#pragma unroll
    for (int r = 0; r < 4; ++r) { acc[r][0] = 0ull; acc[r][1] = 0ull; }
    const float* ap = A + i0;
    const float* bp = B + j0;
#pragma unroll 16
    for (int k = 0; k < 64; ++k) {
        const float4     av = *reinterpret_cast<const float4*>(ap + k * S);
        const ulonglong2 bv = *reinterpret_cast<const ulonglong2*>(bp + k * S);
        const u64 a0 = splat2(av.x), a1 = splat2(av.y);
        const u64 a2 = splat2(av.z), a3 = splat2(av.w);
        fma2(acc[0][0], a0, bv.x); fma2(acc[0][1], a0, bv.y);
        fma2(acc[1][0], a1, bv.x); fma2(acc[1][1], a1, bv.y);
        fma2(acc[2][0], a2, bv.x); fma2(acc[2][1], a2, bv.y);
        fma2(acc[3][0], a3, bv.x); fma2(acc[3][1], a3, bv.y);
    }
}

// acc += c0*I + c1*T on this thread's 4x4 tile.
__device__ __forceinline__ void addlin(u64 acc[4][2],
                                       const float* __restrict__ T,
                                       float c0, float c1, int i0, int j0) {
    const u64 c1s = splat2(c1);
#pragma unroll
    for (int r = 0; r < 4; ++r) {
        const ulonglong2 tv = *reinterpret_cast<const ulonglong2*>(T + (i0 + r) * S + j0);
        fma2(acc[r][0], c1s, tv.x); fma2(acc[r][1], c1s, tv.y);
    }
#pragma unroll
    for (int r = 0; r < 4; ++r) {
        const int cc = i0 + r - j0;            // diag hits tile iff 0 <= cc < 4
        if (cc >= 0 && cc < 4) {
            const u64 d = (cc & 1) ? pack2(0.0f, c0) : pack2(c0, 0.0f);
            add2(acc[r][cc >> 1], d);
        }
    }
}

__device__ __forceinline__ void store_tile(float* __restrict__ C, int stride,
                                           int i0, int j0, const u64 acc[4][2]) {
#pragma unroll
    for (int r = 0; r < 4; ++r)
        *reinterpret_cast<ulonglong2*>(C + (i0 + r) * stride + j0) =
            make_ulonglong2(acc[r][0], acc[r][1]);
}

__global__ __launch_bounds__(256, 3)
void logm_poly_kernel(const float* __restrict__ gin,
                      float* __restrict__ gout,
                      Poly P) {
    extern __shared__ float sm[];
    float* T  = sm;
    float* T2 = sm + 1 * MSZ;
    float* AC = sm + 2 * MSZ;

    const int tid  = threadIdx.x;
    const int warp = tid >> 5;
    const int lane = tid & 31;
    // warps arranged 4 (rows) x 2 (cols); lanes 4 (rows) x 8 (cols).
    const int i0 = (warp >> 1) * 16 + (lane >> 3) * 4;
    const int j0 = (warp & 1) * 32 + (lane & 7) * 4;

    const float* gm = gin  + (size_t)blockIdx.x * 4096;
    float*       go = gout + (size_t)blockIdx.x * 4096;

    const float inv_beta = 1.0f / 2.5f;
    const float alpha    = 3.5f;

    // T = (M - alpha*I) / beta     (lambda(T) in [-1, 1])
    for (int e = tid; e < 1024; e += 256) {
        float4 v = reinterpret_cast<const float4*>(gm)[e];
        const int row = e >> 4;
        const int c0  = (e & 15) * 4;
        if (row >= c0 && row < c0 + 4) {
            float* vv = &v.x;
            vv[row - c0] -= alpha;
        }
        v.x *= inv_beta; v.y *= inv_beta; v.z *= inv_beta; v.w *= inv_beta;
        *reinterpret_cast<float4*>(T + row * S + c0) = v;
    }
    __syncthreads();

    u64 acc[4][2];

    // mm1: T2 = T*T. The acc tile IS this thread's T2 tile, so the innermost
    // Horner chunk  AC = a6*I + a7*T + a8*T2  is free (register combine).
    mm64(T, T, i0, j0, acc);
    store_tile(T2, S, i0, j0, acc);
    {
        u64 c3[4][2];
        const u64 a8s = splat2(P.a[8]);
#pragma unroll
        for (int r = 0; r < 4; ++r) {
            c3[r][0] = 0ull; c3[r][1] = 0ull;
            fma2(c3[r][0], a8s, acc[r][0]);
            fma2(c3[r][1], a8s, acc[r][1]);
        }
        addlin(c3, T, P.a[6], P.a[7], i0, j0);
        store_tile(AC, S, i0, j0, c3);
    }
    __syncthreads();

    // mm2: AC = AC*T2 + a4*I + a5*T
    mm64(AC, T2, i0, j0, acc);
    addlin(acc, T, P.a[4], P.a[5], i0, j0);
    __syncthreads();                       // all reads of old AC complete
    store_tile(AC, S, i0, j0, acc);
    __syncthreads();

    // mm3: AC = AC*T2 + a2*I + a3*T
    mm64(AC, T2, i0, j0, acc);
    addlin(acc, T, P.a[2], P.a[3], i0, j0);
    __syncthreads();
    store_tile(AC, S, i0, j0, acc);
    __syncthreads();

    // mm4 (final): out = AC*T2 + a0*I + a1*T -> global
    mm64(AC, T2, i0, j0, acc);
    addlin(acc, T, P.a[0], P.a[1], i0, j0);
    store_tile(go, 64, i0, j0, acc);
}

extern "C" void kernel_launch(void* const* d_in, const int* in_sizes, int n_in,
                              void* d_out, int out_size) {
    const float* in = (const float*)d_in[0];
    float* out = (float*)d_out;
    const int nmat = in_sizes[0] / 4096;   // 8192 matrices of 64x64

    // Chebyshev coefficients of log on [1,6], converted to monomial basis.
    Poly P;
    {
        const double alpha = 3.5, beta = 2.5;
        const double r = (alpha - sqrt(alpha * alpha - beta * beta)) / beta;
        double c[DEG + 1];
        c[0] = log(alpha / (1.0 + r * r));
        double rk = 1.0;
        for (int k = 1; k <= DEG; ++k) {
            rk *= r;
            c[k] = ((k & 1) ? 2.0 : -2.0) * rk / (double)k;
        }
        double mono[DEG + 1], Tm1[DEG + 1], Tc[DEG + 1], Tn[DEG + 1];
        for (int j = 0; j <= DEG; ++j) { mono[j] = 0; Tm1[j] = 0; Tc[j] = 0; }
        Tm1[0] = 1.0;            // T0
        Tc[1]  = 1.0;            // T1
        for (int j = 0; j <= DEG; ++j) mono[j] = c[0] * Tm1[j] + c[1] * Tc[j];
        for (int k = 2; k <= DEG; ++k) {
            for (int j = 0; j <= DEG; ++j) {
                double t = -Tm1[j];
                if (j > 0) t += 2.0 * Tc[j - 1];
                Tn[j] = t;
            }
            for (int j = 0; j <= DEG; ++j) {
                mono[j] += c[k] * Tn[j];
                Tm1[j] = Tc[j];
                Tc[j]  = Tn[j];
            }
        }
        for (int j = 0; j <= DEG; ++j) P.a[j] = (float)mono[j];
    }

    const size_t smem_bytes = 3 * MSZ * sizeof(float);   // 48 KB
    cudaFuncSetAttribute(logm_poly_kernel,
                         cudaFuncAttributeMaxDynamicSharedMemorySize,
                         (int)smem_bytes);
    logm_poly_kernel<<<nmat, 256, smem_bytes>>>(in, out, P);
}

// round 7
// speedup vs baseline: 2.8648x; 1.6852x over previous
#include <cuda_runtime.h>
#include <cuda_bf16.h>
#include <math.h>
#include <stdint.h>

// Batched log(M) for SPD 64x64 matrices, spectrum in [1, 6]:
// degree-8 Chebyshev poly of log in T = (M - 3.5 I)/2.5, PS s=2 (4 matmuls),
// matmuls on tensor cores via mma.sync m16n8k16 bf16 (HMMA), with 2-way
// bf16 split and 3-term products for fp32-grade accuracy.
// 2 matrices per CTA, 256 threads; warp computes a 32x32 C tile.

constexpr int DEG = 8;
struct Poly { float a[DEG + 1]; };

// per-matrix smem block: 6 bf16 64x64 tiles (8KB each) = 48KB
constexpr int TILE  = 8192;
constexpr int O_TH  = 0 * TILE, O_TL  = 1 * TILE;
constexpr int O_T2H = 2 * TILE, O_T2L = 3 * TILE;
constexpr int O_ACH = 4 * TILE, O_ACL = 5 * TILE;
constexpr int MBLK  = 6 * TILE;          // 48KB
constexpr int SMEM_TOT = 2 * MBLK;       // 96KB

// 16B-granular XOR swizzle: rows are 128B; spread 8 consecutive rows across
// the 8 16B chunks so ldmatrix reads and b32 stores are conflict-free.
__device__ __forceinline__ uint32_t swz(uint32_t b) {
    return b ^ (((b >> 7) & 7u) << 4);
}

__device__ __forceinline__ uint32_t smem_u32(const void* p) {
    uint32_t a;
    asm("{ .reg .u64 t; cvta.to.shared.u64 t, %1; cvt.u32.u64 %0, t; }"
        : "=r"(a) : "l"(p));
    return a;
}
__device__ __forceinline__ void sts32(uint32_t addr, uint32_t v) {
    asm volatile("st.shared.b32 [%0], %1;" :: "r"(addr), "r"(v));
}
__device__ __forceinline__ uint32_t lds32(uint32_t addr) {
    uint32_t v;
    asm volatile("ld.shared.b32 %0, [%1];" : "=r"(v) : "r"(addr));
    return v;
}
// pack two f32 -> bf16x2 (low half = first arg)
__device__ __forceinline__ uint32_t packbf(float lo, float hi) {
    uint32_t r;
    asm("cvt.rn.bf16x2.f32 %0, %1, %2;" : "=r"(r) : "f"(hi), "f"(lo));
    return r;
}
__device__ __forceinline__ float2 unpackbf(uint32_t u) {
    const __nv_bfloat162 b = *reinterpret_cast<const __nv_bfloat162*>(&u);
    return make_float2(__bfloat162float(b.x), __bfloat162float(b.y));
}
__device__ __forceinline__ float bf_hi(float x) {
    return __bfloat162float(__float2bfloat16_rn(x));
}

__device__ __forceinline__ void ldsm4(uint32_t r[4], uint32_t addr) {
    asm volatile("ldmatrix.sync.aligned.m8n8.x4.shared.b16 {%0,%1,%2,%3}, [%4];"
                 : "=r"(r[0]), "=r"(r[1]), "=r"(r[2]), "=r"(r[3]) : "r"(addr));
}
__device__ __forceinline__ void mma16816(float c[4], const uint32_t a[4],
                                         uint32_t b0, uint32_t b1) {
    asm volatile(
        "mma.sync.aligned.m16n8k16.row.col.f32.bf16.bf16.f32 "
        "{%0,%1,%2,%3}, {%4,%5,%6,%7}, {%8,%9}, {%0,%1,%2,%3};"
        : "+f"(c[0]), "+f"(c[1]), "+f"(c[2]), "+f"(c[3])
        : "r"(a[0]), "r"(a[1]), "r"(a[2]), "r"(a[3]), "r"(b0), "r"(b1));
}

// C(32x32) = X * Y^T restricted to symmetric X, Y (== X*Y). X, Y row-major
// k-contiguous bf16 hi/lo tiles. 3-term split product, f32 accumulate.
__device__ __forceinline__ void mm32x32(uint32_t Xh, uint32_t Xl,
                                        uint32_t Yh, uint32_t Yl,
                                        int row0, int col0, int lane,
                                        float acc[8][4]) {
#pragma unroll
    for (int t = 0; t < 8; ++t)
#pragma unroll
        for (int e = 0; e < 4; ++e) acc[t][e] = 0.0f;

    const int la = lane & 15, lc = lane >> 4;
#pragma unroll
    for (int ks = 0; ks < 4; ++ks) {
        uint32_t ah[2][4], al[2][4], bh[2][4], bl[2][4];
#pragma unroll
        for (int mi = 0; mi < 2; ++mi) {
            const uint32_t off =
                swz((uint32_t)((row0 + mi * 16 + la) * 128 + ks * 32 + lc * 16));
            ldsm4(ah[mi], Xh + off);
            ldsm4(al[mi], Xl + off);
        }
#pragma unroll
        for (int nj = 0; nj < 2; ++nj) {
            const uint32_t off =
                swz((uint32_t)((col0 + nj * 16 + la) * 128 + ks * 32 + lc * 16));
            ldsm4(bh[nj], Yh + off);
            ldsm4(bl[nj], Yl + off);
        }
        // x4 tile order: [n0-7,k0-7],[n8-15,k0-7],[n0-7,k8-15],[n8-15,k8-15]
        // n8 tile ni: group nj = ni>>1, sub = ni&1 -> b-frag {r[sub], r[sub+2]}
#pragma unroll
        for (int mi = 0; mi < 2; ++mi)
#pragma unroll
            for (int ni = 0; ni < 4; ++ni) {
                const int nj = ni >> 1, sub = ni & 1;
                float* c = acc[mi * 4 + ni];
                mma16816(c, ah[mi], bh[nj][sub], bh[nj][sub + 2]);  // Ah*Bh
                mma16816(c, ah[mi], bl[nj][sub], bl[nj][sub + 2]);  // Ah*Bl
                mma16816(c, al[mi], bh[nj][sub], bh[nj][sub + 2]);  // Al*Bh
            }
    }
}

__global__ __launch_bounds__(256, 2)
void logm_hmma_kernel(const float* __restrict__ gin,
                      float* __restrict__ gout,
                      Poly P) {
    extern __shared__ char smc[];
    const uint32_t sb = smem_u32(smc);

    const int tid  = threadIdx.x;
    const int warp = tid >> 5;
    const int lane = tid & 31;
    const int m    = warp >> 2;                 // matrix of the pair
    const int q    = warp & 3;
    const int row0 = (q >> 1) * 32;
    const int col0 = (q & 1) * 32;
    const uint32_t mb = sb + (uint32_t)m * MBLK;

    // ---- prologue: T = (M - 3.5 I)/2.5, split-store Th/Tl
    {
        const int pm = tid >> 7;                // matrix handled by this thread
        const int pr = (tid & 127) >> 1;        // row 0..63
        const int ph = tid & 1;                 // col half
        const float* gp = gin + ((size_t)(2 * blockIdx.x + pm)) * 4096
                        + pr * 64 + ph * 32;
        float v[32];
#pragma unroll
        for (int j = 0; j < 32; j += 4) {
            const float4 t4 = *reinterpret_cast<const float4*>(gp + j);
            v[j] = t4.x; v[j + 1] = t4.y; v[j + 2] = t4.z; v[j + 3] = t4.w;
        }
        const float inv_beta = 1.0f / 2.5f, alpha = 3.5f;
#pragma unroll
        for (int j = 0; j < 32; ++j)
            v[j] = (v[j] - ((ph * 32 + j == pr) ? alpha : 0.0f)) * inv_beta;

        const uint32_t tb = sb + (uint32_t)pm * MBLK;
#pragma unroll
        for (int j = 0; j < 16; ++j) {
            const int c = ph * 32 + 2 * j;
            const uint32_t off = swz((uint32_t)(pr * 128 + c * 2));
            const float x0 = v[2 * j], x1 = v[2 * j + 1];
            const float h0 = bf_hi(x0), h1 = bf_hi(x1);
            sts32(tb + O_TH + off, packbf(h0, h1));
            sts32(tb + O_TL + off, packbf(x0 - h0, x1 - h1));
        }
    }
    __syncthreads();

    float acc[8][4];

    for (int step = 0; step < 4; ++step) {
        uint32_t Xh, Xl, Yh, Yl;
        if (step == 0) { Xh = mb + O_TH;  Xl = mb + O_TL;  Yh = mb + O_TH;  Yl = mb + O_TL; }
        else           { Xh = mb + O_ACH; Xl = mb + O_ACL; Yh = mb + O_T2H; Yl = mb + O_T2L; }

        mm32x32(Xh, Xl, Yh, Yl, row0, col0, lane, acc);
        __syncthreads();                  // all ldmatrix reads complete

        float cd, c1, cc0;
        if      (step == 0) { cd = P.a[8]; c1 = P.a[7]; cc0 = P.a[6]; }
        else if (step == 1) { cd = 1.0f;   c1 = P.a[5]; cc0 = P.a[4]; }
        else if (step == 2) { cd = 1.0f;   c1 = P.a[3]; cc0 = P.a[2]; }
        else                { cd = 1.0f;   c1 = P.a[1]; cc0 = P.a[0]; }

#pragma unroll
        for (int mi = 0; mi < 2; ++mi)
#pragma unroll
            for (int ni = 0; ni < 4; ++ni) {
                const float* c = acc[mi * 4 + ni];
#pragma unroll
                for (int hf = 0; hf < 2; ++hf) {
                    const int gr = row0 + mi * 16 + (lane >> 2) + hf * 8;
                    const int gc = col0 + ni * 8 + (lane & 3) * 2;
                    const uint32_t off = swz((uint32_t)(gr * 128 + gc * 2));
                    const float2 th = unpackbf(lds32(mb + O_TH + off));
                    const float2 tl = unpackbf(lds32(mb + O_TL + off));
                    float x0 = cd * c[2 * hf]     + c1 * (th.x + tl.x);
                    float x1 = cd * c[2 * hf + 1] + c1 * (th.y + tl.y);
                    if (gr == gc)     x0 += cc0;
                    if (gr == gc + 1) x1 += cc0;
                    if (step < 3) {
                        const float h0 = bf_hi(x0), h1 = bf_hi(x1);
                        sts32(mb + O_ACH + off, packbf(h0, h1));
                        sts32(mb + O_ACL + off, packbf(x0 - h0, x1 - h1));
                        if (step == 0) {          // raw acc IS T2
                            const float d0 = c[2 * hf], d1 = c[2 * hf + 1];
                            const float g0 = bf_hi(d0), g1 = bf_hi(d1);
                            sts32(mb + O_T2H + off, packbf(g0, g1));
                            sts32(mb + O_T2L + off, packbf(d0 - g0, d1 - g1));
                        }
                    } else {
                        float2* gp = reinterpret_cast<float2*>(
                            gout + (size_t)(2 * blockIdx.x + m) * 4096 + gr * 64 + gc);
                        *gp = make_float2(x0, x1);
                    }
                }
            }
        if (step < 3) __syncthreads();    // writes visible before next mm reads
    }
}

extern "C" void kernel_launch(void* const* d_in, const int* in_sizes, int n_in,
                              void* d_out, int out_size) {
    const float* in = (const float*)d_in[0];
    float* out = (float*)d_out;
    const int nmat = in_sizes[0] / 4096;   // 8192 matrices of 64x64

    // Chebyshev coefficients of log on [1,6], converted to monomial basis.
    Poly P;
    {
        const double alpha = 3.5, beta = 2.5;
        const double r = (alpha - sqrt(alpha * alpha - beta * beta)) / beta;
        double c[DEG + 1];
        c[0] = log(alpha / (1.0 + r * r));
        double rk = 1.0;
        for (int k = 1; k <= DEG; ++k) {
            rk *= r;
            c[k] = ((k & 1) ? 2.0 : -2.0) * rk / (double)k;
        }
        double mono[DEG + 1], Tm1[DEG + 1], Tc[DEG + 1], Tn[DEG + 1];
        for (int j = 0; j <= DEG; ++j) { mono[j] = 0; Tm1[j] = 0; Tc[j] = 0; }
        Tm1[0] = 1.0;            // T0
        Tc[1]  = 1.0;            // T1
        for (int j = 0; j <= DEG; ++j) mono[j] = c[0] * Tm1[j] + c[1] * Tc[j];
        for (int k = 2; k <= DEG; ++k) {
            for (int j = 0; j <= DEG; ++j) {
                double t = -Tm1[j];
                if (j > 0) t += 2.0 * Tc[j - 1];
                Tn[j] = t;
            }
            for (int j = 0; j <= DEG; ++j) {
                mono[j] += c[k] * Tn[j];
                Tm1[j] = Tc[j];
                Tc[j]  = Tn[j];
            }
        }
        for (int j = 0; j <= DEG; ++j) P.a[j] = (float)mono[j];
    }

    cudaFuncSetAttribute(logm_hmma_kernel,
                         cudaFuncAttributeMaxDynamicSharedMemorySize, SMEM_TOT);
    logm_hmma_kernel<<<nmat / 2, 256, SMEM_TOT>>>(in, out, P);
}

// round 8
// speedup vs baseline: 3.6748x; 1.2827x over previous
#include <cuda_runtime.h>
#include <cuda_bf16.h>
#include <math.h>
#include <stdint.h>

// Batched log(M) for SPD 64x64 matrices, spectrum in [1, 6]:
// degree-8 Chebyshev poly of log in T = (M - 3.5 I)/2.5, PS s=2 (4 matmuls),
// tensor cores via mma.sync m16n8k16 bf16 (HMMA), 2-way bf16 split, 3-term
// products. 1 matrix per CTA (128 threads, 4 warps, 4 CTAs/SM), ping-pong AC
// buffers (1 barrier/step), T fragments + all swizzled offsets in registers.

constexpr int DEG = 8;
struct Poly { float a[DEG + 1]; };

constexpr int TILE = 8192;           // one 64x64 bf16 tile
constexpr int SMEM_TOT = 6 * TILE;   // Th,Tl | T2h,T2l | ACh,ACl  (48KB)

__device__ __forceinline__ uint32_t smem_u32(const void* p) {
    uint32_t a;
    asm("{ .reg .u64 t; cvta.to.shared.u64 t, %1; cvt.u32.u64 %0, t; }"
        : "=r"(a) : "l"(p));
    return a;
}
__device__ __forceinline__ void sts32(uint32_t addr, uint32_t v) {
    asm volatile("st.shared.b32 [%0], %1;" :: "r"(addr), "r"(v));
}
__device__ __forceinline__ uint32_t lds32(uint32_t addr) {
    uint32_t v;
    asm volatile("ld.shared.b32 %0, [%1];" : "=r"(v) : "r"(addr));
    return v;
}
// pack two f32 -> bf16x2 (low half = first arg)
__device__ __forceinline__ uint32_t packbf(float lo, float hi) {
    uint32_t r;
    asm("cvt.rn.bf16x2.f32 %0, %1, %2;" : "=r"(r) : "f"(hi), "f"(lo));
    return r;
}
__device__ __forceinline__ float2 unpackbf(uint32_t u) {
    const __nv_bfloat162 b = *reinterpret_cast<const __nv_bfloat162*>(&u);
    return make_float2(__bfloat162float(b.x), __bfloat162float(b.y));
}
__device__ __forceinline__ float bf_hi(float x) {
    return __bfloat162float(__float2bfloat16_rn(x));
}
__device__ __forceinline__ void ldsm4(uint32_t r[4], uint32_t addr) {
    asm volatile("ldmatrix.sync.aligned.m8n8.x4.shared.b16 {%0,%1,%2,%3}, [%4];"
                 : "=r"(r[0]), "=r"(r[1]), "=r"(r[2]), "=r"(r[3]) : "r"(addr));
}
__device__ __forceinline__ void mma16816(float c[4], const uint32_t a[4],
                                         uint32_t b0, uint32_t b1) {
    asm volatile(
        "mma.sync.aligned.m16n8k16.row.col.f32.bf16.bf16.f32 "
        "{%0,%1,%2,%3}, {%4,%5,%6,%7}, {%8,%9}, {%0,%1,%2,%3};"
        : "+f"(c[0]), "+f"(c[1]), "+f"(c[2]), "+f"(c[3])
        : "r"(a[0]), "r"(a[1]), "r"(a[2]), "r"(a[3]), "r"(b0), "r"(b1));
}

// C(32x32) = X * Y^T (== X*Y when Y symmetric). X,Y row-major k-contiguous
// bf16 hi tiles at Xh/Yh, lo tiles at +TILE. rX*/rY* are precomputed raw
// (unswizzled) byte offsets; msk is the per-thread swizzle XOR (row-invariant;
// all in-loop adds stay below bit 7, so XOR-after-add is the exact swizzle).
__device__ __forceinline__ void mm32x32(uint32_t Xh, uint32_t Yh,
                                        uint32_t rX0, uint32_t rX1,
                                        uint32_t rY0, uint32_t rY1,
                                        uint32_t msk, float acc[8][4]) {
#pragma unroll
    for (int t = 0; t < 8; ++t)
#pragma unroll
        for (int e = 0; e < 4; ++e) acc[t][e] = 0.0f;

#pragma unroll
    for (int ks = 0; ks < 4; ++ks) {
        const uint32_t kofs = (uint32_t)(ks * 32);
        const uint32_t aX0 = Xh + ((rX0 + kofs) ^ msk);
        const uint32_t aX1 = Xh + ((rX1 + kofs) ^ msk);
        const uint32_t aY0 = Yh + ((rY0 + kofs) ^ msk);
        const uint32_t aY1 = Yh + ((rY1 + kofs) ^ msk);
        uint32_t ah[2][4], al[2][4], bh[2][4], bl[2][4];
        ldsm4(ah[0], aX0); ldsm4(al[0], aX0 + TILE);
        ldsm4(ah[1], aX1); ldsm4(al[1], aX1 + TILE);
        ldsm4(bh[0], aY0); ldsm4(bl[0], aY0 + TILE);
        ldsm4(bh[1], aY1); ldsm4(bl[1], aY1 + TILE);
        // x4 tile order: [n0-7,k0-7],[n8-15,k0-7],[n0-7,k8-15],[n8-15,k8-15]
#pragma unroll
        for (int mi = 0; mi < 2; ++mi)
#pragma unroll
            for (int ni = 0; ni < 4; ++ni) {
                const int nj = ni >> 1, sub = ni & 1;
                float* c = acc[mi * 4 + ni];
                mma16816(c, ah[mi], bh[nj][sub], bh[nj][sub + 2]);  // Ah*Bh
                mma16816(c, ah[mi], bl[nj][sub], bl[nj][sub + 2]);  // Ah*Bl
                mma16816(c, al[mi], bh[nj][sub], bh[nj][sub + 2]);  // Al*Bh
            }
    }
}

__global__ __launch_bounds__(128, 4)
void logm_hmma_kernel(const float* __restrict__ gin,
                      float* __restrict__ gout,
                      Poly P) {
    extern __shared__ char smc[];
    const uint32_t sb  = smem_u32(smc);
    const uint32_t bTh = sb,             bTl  = sb + TILE;      // pong after step1
    const uint32_t bT2 = sb + 2 * TILE;                         // T2h (+TILE = T2l)
    const uint32_t bP  = sb + 4 * TILE;                         // ping ACh (+TILE = ACl)

    const int tid  = threadIdx.x;
    const int warp = tid >> 5;
    const int lane = tid & 31;
    const int row0 = (warp >> 1) * 32;
    const int col0 = (warp & 1) * 32;

    // ---- prologue: T = (M - 3.5 I)/2.5, split-store Th/Tl
    {
        const int pr = tid >> 1, ph = tid & 1;
        const float* gp = gin + (size_t)blockIdx.x * 4096 + pr * 64 + ph * 32;
        float v[32];
#pragma unroll
        for (int j = 0; j < 32; j += 4) {
            const float4 t4 = *reinterpret_cast<const float4*>(gp + j);
            v[j] = t4.x; v[j + 1] = t4.y; v[j + 2] = t4.z; v[j + 3] = t4.w;
        }
        const float inv_beta = 1.0f / 2.5f, alpha = 3.5f;
#pragma unroll
        for (int j = 0; j < 32; ++j)
            v[j] = (v[j] - ((ph * 32 + j == pr) ? alpha : 0.0f)) * inv_beta;

        const uint32_t pmsk = (uint32_t)((pr & 7) << 4);
#pragma unroll
        for (int j = 0; j < 16; ++j) {
            const uint32_t off = ((uint32_t)(pr * 128 + ph * 64 + 4 * j)) ^ pmsk;
            const float x0 = v[2 * j], x1 = v[2 * j + 1];
            const float h0 = bf_hi(x0), h1 = bf_hi(x1);
            sts32(bTh + off, packbf(h0, h1));
            sts32(bTl + off, packbf(x0 - h0, x1 - h1));
        }
    }
    __syncthreads();

    // ---- per-thread constant geometry (registers)
    const int la = lane & 15, lc = lane >> 4;
    const uint32_t msk = (uint32_t)((la & 7) << 4);
    const uint32_t rX0 = (uint32_t)((row0 + la) * 128 + lc * 16);
    const uint32_t rX1 = rX0 + 16 * 128;
    const uint32_t rY0 = (uint32_t)((col0 + la) * 128 + lc * 16);
    const uint32_t rY1 = rY0 + 16 * 128;

    const int er = lane >> 2, ec = (lane & 3) * 2;
    const uint32_t mskE = (uint32_t)((er & 7) << 4);
    const uint32_t rE0  = (uint32_t)((row0 + er) * 128 + (col0 + ec) * 2);

    // T fragments (hoisted: epilogue never touches smem-T again), diag masks,
    // precomputed swizzled epilogue offsets.
    float2   Treg[16];
    uint32_t eoff[16];
    uint32_t dm0 = 0, dm1 = 0;
#pragma unroll
    for (int mi = 0; mi < 2; ++mi)
#pragma unroll
        for (int ni = 0; ni < 4; ++ni)
#pragma unroll
            for (int hf = 0; hf < 2; ++hf) {
                const int pos = mi * 8 + ni * 2 + hf;
                const uint32_t rel =
                    (rE0 + (uint32_t)(mi * 2048 + ni * 16 + hf * 1024)) ^ mskE;
                eoff[pos] = rel;
                const float2 th = unpackbf(lds32(bTh + rel));
                const float2 tl = unpackbf(lds32(bTl + rel));
                Treg[pos] = make_float2(th.x + tl.x, th.y + tl.y);
                const int gr = row0 + mi * 16 + er + hf * 8;
                const int gc = col0 + ni * 8 + ec;
                if (gr == gc)     dm0 |= 1u << pos;
                if (gr == gc + 1) dm1 |= 1u << pos;
            }

    float acc[8][4];

#pragma unroll
    for (int step = 0; step < 4; ++step) {
        // buffers: step0 X=Y=T; steps>=1 Y=T2, X alternates ping/pong
        const uint32_t Xh = (step == 0) ? bTh : ((step & 1) ? bP : bTh);
        const uint32_t Yh = (step == 0) ? bTh : bT2;
        const uint32_t Wh = (step & 1) ? bTh : bP;   // write target (unused step3)

        mm32x32(Xh, Yh, rX0, rX1, rY0, rY1, msk, acc);

        float cd, c1, cc0;
        if      (step == 0) { cd = P.a[8]; c1 = P.a[7]; cc0 = P.a[6]; }
        else if (step == 1) { cd = 1.0f;   c1 = P.a[5]; cc0 = P.a[4]; }
        else if (step == 2) { cd = 1.0f;   c1 = P.a[3]; cc0 = P.a[2]; }
        else                { cd = 1.0f;   c1 = P.a[1]; cc0 = P.a[0]; }

#pragma unroll
        for (int mi = 0; mi < 2; ++mi)
#pragma unroll
            for (int ni = 0; ni < 4; ++ni) {
                const float* c = acc[mi * 4 + ni];
#pragma unroll
                for (int hf = 0; hf < 2; ++hf) {
                    const int pos = mi * 8 + ni * 2 + hf;
                    const uint32_t rel = eoff[pos];
                    float x0 = cd * c[2 * hf]     + c1 * Treg[pos].x;
                    float x1 = cd * c[2 * hf + 1] + c1 * Treg[pos].y;
                    if ((dm0 >> pos) & 1) x0 += cc0;
                    if ((dm1 >> pos) & 1) x1 += cc0;
                    if (step < 3) {
                        const float h0 = bf_hi(x0), h1 = bf_hi(x1);
                        sts32(Wh + rel,        packbf(h0, h1));
                        sts32(Wh + TILE + rel, packbf(x0 - h0, x1 - h1));
                        if (step == 0) {       // raw acc IS T2
                            const float d0 = c[2 * hf], d1 = c[2 * hf + 1];
                            const float g0 = bf_hi(d0), g1 = bf_hi(d1);
                            sts32(bT2 + rel,        packbf(g0, g1));
                            sts32(bT2 + TILE + rel, packbf(d0 - g0, d1 - g1));
                        }
                    } else {
                        const int gr = row0 + mi * 16 + er + hf * 8;
                        const int gc = col0 + ni * 8 + ec;
                        float2* gp = reinterpret_cast<float2*>(
                            gout + (size_t)blockIdx.x * 4096 + gr * 64 + gc);
                        *gp = make_float2(x0, x1);
                    }
                }
            }
        if (step < 3) __syncthreads();   // single barrier per step (ping-pong)
    }
}

extern "C" void kernel_launch(void* const* d_in, const int* in_sizes, int n_in,
                              void* d_out, int out_size) {
    const float* in = (const float*)d_in[0];
    float* out = (float*)d_out;
    const int nmat = in_sizes[0] / 4096;   // 8192 matrices of 64x64

    // Chebyshev coefficients of log on [1,6], converted to monomial basis.
    Poly P;
    {
        const double alpha = 3.5, beta = 2.5;
        const double r = (alpha - sqrt(alpha * alpha - beta * beta)) / beta;
        double c[DEG + 1];
        c[0] = log(alpha / (1.0 + r * r));
        double rk = 1.0;
        for (int k = 1; k <= DEG; ++k) {
            rk *= r;
            c[k] = ((k & 1) ? 2.0 : -2.0) * rk / (double)k;
        }
        double mono[DEG + 1], Tm1[DEG + 1], Tc[DEG + 1], Tn[DEG + 1];
        for (int j = 0; j <= DEG; ++j) { mono[j] = 0; Tm1[j] = 0; Tc[j] = 0; }
        Tm1[0] = 1.0;            // T0
        Tc[1]  = 1.0;            // T1
        for (int j = 0; j <= DEG; ++j) mono[j] = c[0] * Tm1[j] + c[1] * Tc[j];
        for (int k = 2; k <= DEG; ++k) {
            for (int j = 0; j <= DEG; ++j) {
                double t = -Tm1[j];
                if (j > 0) t += 2.0 * Tc[j - 1];
                Tn[j] = t;
            }
            for (int j = 0; j <= DEG; ++j) {
                mono[j] += c[k] * Tn[j];
                Tm1[j] = Tc[j];
                Tc[j]  = Tn[j];
            }
        }
        for (int j = 0; j <= DEG; ++j) P.a[j] = (float)mono[j];
    }

    cudaFuncSetAttribute(logm_hmma_kernel,
                         cudaFuncAttributeMaxDynamicSharedMemorySize, SMEM_TOT);
    logm_hmma_kernel<<<nmat, 128, SMEM_TOT>>>(in, out, P);
}